// round 5
// baseline (speedup 1.0000x reference)
#include <cuda_runtime.h>
#include <math.h>

#define N_NODES 100000
#define N_EDGES 1600000
#define DIM 128

// ---------------- scratch (no allocations allowed) ----------------
__device__ int   g_deg[N_NODES];
__device__ int   g_off[N_NODES + 1];
__device__ int   g_cur[N_NODES];
__device__ int   g_csr[N_EDGES];
__device__ float g_agg[(size_t)N_NODES * DIM];   // reused: layer0 agg, then layer1/2 agg
__device__ float g_h[(size_t)N_NODES * DIM];
__device__ float g_W0[256 * 128];                // [w_self0 ; w_neigh0]
__device__ float g_W12[256 * 128];               // [ws1|ws2 interleaved ; wn1|wn2 interleaved]
__device__ float g_b12[128];                     // interleaved b1/b2

// ---------------- CSR build ----------------
__global__ void zero_deg_kernel() {
    int i = blockIdx.x * blockDim.x + threadIdx.x;
    if (i < N_NODES) g_deg[i] = 0;
}

__global__ void degree_kernel(const int* __restrict__ dst) {
    int e = blockIdx.x * blockDim.x + threadIdx.x;
    if (e < N_EDGES) atomicAdd(&g_deg[dst[e]], 1);
}

// single-block exclusive scan over N_NODES degrees -> offsets + cursors
__global__ void scan_kernel() {
    __shared__ int wsum[32];
    __shared__ int carry_sh;
    const int tid  = threadIdx.x;
    const int lane = tid & 31, wid = tid >> 5;
    if (tid == 0) carry_sh = 0;
    __syncthreads();
    for (int base = 0; base < N_NODES; base += 1024) {
        int i = base + tid;
        int v = (i < N_NODES) ? g_deg[i] : 0;
        int x = v;
        #pragma unroll
        for (int d = 1; d < 32; d <<= 1) {
            int y = __shfl_up_sync(0xffffffffu, x, d);
            if (lane >= d) x += y;
        }
        if (lane == 31) wsum[wid] = x;
        __syncthreads();
        if (wid == 0) {
            int s = wsum[lane];
            #pragma unroll
            for (int d = 1; d < 32; d <<= 1) {
                int y = __shfl_up_sync(0xffffffffu, s, d);
                if (lane >= d) s += y;
            }
            wsum[lane] = s;
        }
        __syncthreads();
        int carry = carry_sh;
        int excl = carry + (wid ? wsum[wid - 1] : 0) + x - v;
        if (i < N_NODES) { g_off[i] = excl; g_cur[i] = excl; }
        __syncthreads();
        if (tid == 0) carry_sh = carry + wsum[31];
        __syncthreads();
    }
    if (tid == 0) g_off[N_NODES] = carry_sh;
}

__global__ void fill_kernel(const int* __restrict__ src, const int* __restrict__ dst) {
    int e = blockIdx.x * blockDim.x + threadIdx.x;
    if (e < N_EDGES) {
        int p = atomicAdd(&g_cur[dst[e]], 1);
        g_csr[p] = src[e];
    }
}

// ---------------- aggregation: one warp per node, mean over in-edges ----------------
// PHASE 0: x = features (kernel arg).  PHASE 1: x = g_h.  Output always g_agg.
template <int PHASE>
__global__ void agg_kernel(const float* __restrict__ xin) {
    const float* __restrict__ x = (PHASE == 0) ? xin : g_h;
    int w = (blockIdx.x * blockDim.x + threadIdx.x) >> 5;
    int lane = threadIdx.x & 31;
    if (w >= N_NODES) return;
    int beg = g_off[w], end = g_off[w + 1];
    float4 acc = make_float4(0.f, 0.f, 0.f, 0.f);
    int i = beg;
    for (; i + 4 <= end; i += 4) {
        int s0 = g_csr[i], s1 = g_csr[i + 1], s2 = g_csr[i + 2], s3 = g_csr[i + 3];
        float4 v0 = *((const float4*)(x + (size_t)s0 * DIM) + lane);
        float4 v1 = *((const float4*)(x + (size_t)s1 * DIM) + lane);
        float4 v2 = *((const float4*)(x + (size_t)s2 * DIM) + lane);
        float4 v3 = *((const float4*)(x + (size_t)s3 * DIM) + lane);
        acc.x += v0.x + v1.x + v2.x + v3.x;
        acc.y += v0.y + v1.y + v2.y + v3.y;
        acc.z += v0.z + v1.z + v2.z + v3.z;
        acc.w += v0.w + v1.w + v2.w + v3.w;
    }
    for (; i < end; i++) {
        int s = g_csr[i];
        float4 v = *((const float4*)(x + (size_t)s * DIM) + lane);
        acc.x += v.x; acc.y += v.y; acc.z += v.z; acc.w += v.w;
    }
    float inv = (end > beg) ? 1.0f / (float)(end - beg) : 0.0f;
    acc.x *= inv; acc.y *= inv; acc.z *= inv; acc.w *= inv;
    *((float4*)(g_agg + (size_t)w * DIM) + lane) = acc;
}

// ---------------- weight prep: pack/concat/interleave once per launch ----------------
__global__ void prep_weights(const float* __restrict__ ws0, const float* __restrict__ wn0,
                             const float* __restrict__ ws1, const float* __restrict__ wn1,
                             const float* __restrict__ ws2, const float* __restrict__ wn2,
                             const float* __restrict__ b1,  const float* __restrict__ b2) {
    int idx = blockIdx.x * blockDim.x + threadIdx.x;   // 0 .. 32767
    if (idx >= 256 * 128) return;
    int k = idx >> 7, j = idx & 127;
    // W0: straight concat [ws0 ; wn0], both (128,128)
    g_W0[idx] = (k < 128) ? ws0[k * 128 + j] : wn0[(k - 128) * 128 + j];
    // W12: column j in group g=j/8, slot w=j%8; w<4 -> mean col m, else log_std col m
    int g = j >> 3, w = j & 7;
    int m = g * 4 + (w & 3);
    int kk = k & 127;
    const float* Wsel;
    if (k < 128) Wsel = (w < 4) ? ws1 : ws2;   // self path (applied to h)
    else         Wsel = (w < 4) ? wn1 : wn2;   // neigh path (applied to agg(h))
    g_W12[idx] = Wsel[kk * 64 + m];            // (128,64) matrices
    if (idx < 128) {
        int gg = idx >> 3, ww = idx & 7;
        int mm = gg * 4 + (ww & 3);
        g_b12[idx] = (ww < 4) ? b1[mm] : b2[mm];
    }
}

// ---------------- fused dual-input GEMM ----------------
// MODE 0: h = relu(features @ Ws0 + agg @ Wn0 + b0)          -> g_h   [N,128]
// MODE 1: out = mean + noise*exp(log_std), cols interleaved  -> d_out [N,64]
template <int MODE>
__global__ void __launch_bounds__(256, 2)
gemm_kernel(const float* __restrict__ A0in, const float* __restrict__ bias,
            const float* __restrict__ noise, float* __restrict__ outp) {
    const float* __restrict__ A0 = (MODE == 0) ? A0in : g_h;   // MODE-1 A0 is g_h
    const float* __restrict__ A1 = g_agg;
    const float* __restrict__ W  = (MODE == 0) ? g_W0 : g_W12;
    __shared__ float sA[16][128];   // [k][row]
    __shared__ float sB[16][128];   // [k][col]
    const int row0 = blockIdx.x * 128;
    const int t = threadIdx.x;
    const int tx = t & 15, ty = t >> 4;

    float acc[8][8];
    #pragma unroll
    for (int i = 0; i < 8; i++)
        #pragma unroll
        for (int j = 0; j < 8; j++) acc[i][j] = 0.f;

    for (int k0 = 0; k0 < 256; k0 += 16) {
        const float* A = (k0 < 128) ? A0 : A1;
        const int kb = k0 & 127;
        // A tile: 128 rows x 16 k (stored transposed)
        #pragma unroll
        for (int i = 0; i < 2; i++) {
            int idx = t + i * 256;          // float4 index 0..511
            int r = idx >> 2, c4 = idx & 3;
            float4 v = make_float4(0.f, 0.f, 0.f, 0.f);
            int grow = row0 + r;
            if (grow < N_NODES) v = *(const float4*)(A + (size_t)grow * 128 + kb + c4 * 4);
            sA[c4 * 4 + 0][r] = v.x;
            sA[c4 * 4 + 1][r] = v.y;
            sA[c4 * 4 + 2][r] = v.z;
            sA[c4 * 4 + 3][r] = v.w;
        }
        // B tile: 16 k x 128 cols
        #pragma unroll
        for (int i = 0; i < 2; i++) {
            int idx = t + i * 256;
            int r = idx >> 5, c4 = idx & 31;
            *(float4*)&sB[r][c4 * 4] = *(const float4*)(W + (size_t)(k0 + r) * 128 + c4 * 4);
        }
        __syncthreads();
        #pragma unroll
        for (int k = 0; k < 16; k++) {
            float a[8], bb[8];
            *(float4*)&a[0]  = *(const float4*)&sA[k][ty * 8];
            *(float4*)&a[4]  = *(const float4*)&sA[k][ty * 8 + 4];
            *(float4*)&bb[0] = *(const float4*)&sB[k][tx * 8];
            *(float4*)&bb[4] = *(const float4*)&sB[k][tx * 8 + 4];
            #pragma unroll
            for (int i = 0; i < 8; i++)
                #pragma unroll
                for (int j = 0; j < 8; j++)
                    acc[i][j] = fmaf(a[i], bb[j], acc[i][j]);
        }
        __syncthreads();
    }

    if (MODE == 0) {
        #pragma unroll
        for (int i = 0; i < 8; i++) {
            int grow = row0 + ty * 8 + i;
            if (grow < N_NODES) {
                #pragma unroll
                for (int j = 0; j < 8; j++) {
                    int col = tx * 8 + j;
                    g_h[(size_t)grow * 128 + col] = fmaxf(acc[i][j] + bias[col], 0.f);
                }
            }
        }
    } else {
        #pragma unroll
        for (int i = 0; i < 8; i++) {
            int grow = row0 + ty * 8 + i;
            if (grow < N_NODES) {
                #pragma unroll
                for (int j = 0; j < 4; j++) {
                    int oc = tx * 4 + j;
                    float mean = acc[i][j]     + g_b12[tx * 8 + j];
                    float ls   = acc[i][j + 4] + g_b12[tx * 8 + 4 + j];
                    outp[(size_t)grow * 64 + oc] =
                        fmaf(noise[(size_t)grow * 64 + oc], expf(ls), mean);
                }
            }
        }
    }
}

// ---------------- launch: pure kernel launches, nothing else ----------------
extern "C" void kernel_launch(void* const* d_in, const int* in_sizes, int n_in,
                              void* d_out, int out_size) {
    const float* features = (const float*)d_in[0];
    const int*   src      = (const int*)  d_in[1];
    const int*   dst      = (const int*)  d_in[2];
    const float* noise    = (const float*)d_in[3];
    const float* ws0      = (const float*)d_in[4];
    const float* wn0      = (const float*)d_in[5];
    const float* b0       = (const float*)d_in[6];
    const float* ws1      = (const float*)d_in[7];
    const float* wn1      = (const float*)d_in[8];
    const float* b1       = (const float*)d_in[9];
    const float* ws2      = (const float*)d_in[10];
    const float* wn2      = (const float*)d_in[11];
    const float* b2       = (const float*)d_in[12];
    float* out = (float*)d_out;

    const int EB = N_EDGES / 256;              // 6250, exact
    const int GEMM_BLOCKS = (N_NODES + 127) / 128;
    const int AGG_BLOCKS  = (N_NODES * 32 + 255) / 256;

    zero_deg_kernel<<<(N_NODES + 255) / 256, 256>>>();
    prep_weights<<<128, 256>>>(ws0, wn0, ws1, wn1, ws2, wn2, b1, b2);
    degree_kernel<<<EB, 256>>>(dst);
    scan_kernel<<<1, 1024>>>();
    fill_kernel<<<EB, 256>>>(src, dst);

    // layer 0
    agg_kernel<0><<<AGG_BLOCKS, 256>>>(features);
    gemm_kernel<0><<<GEMM_BLOCKS, 256>>>(features, b0, nullptr, nullptr);

    // layers 1 & 2 fused (one aggregation of h serves both mean and log_std)
    agg_kernel<1><<<AGG_BLOCKS, 256>>>(nullptr);
    gemm_kernel<1><<<GEMM_BLOCKS, 256>>>(nullptr, nullptr, noise, out);
}

// round 6
// speedup vs baseline: 1.1174x; 1.1174x over previous
#include <cuda_runtime.h>
#include <math.h>

#define N_NODES 100000
#define N_EDGES 1600000
#define DIM 128
#define SCAN_BLK 2048
#define SCAN_NBLK ((N_NODES + SCAN_BLK - 1) / SCAN_BLK)   // 49

// ---------------- scratch (no allocations allowed) ----------------
__device__ int   g_deg[N_NODES];
__device__ int   g_off[N_NODES + 1];
__device__ int   g_cur[N_NODES];
__device__ int   g_blk[SCAN_NBLK];
__device__ int   g_csr[N_EDGES];
__device__ float g_agg[(size_t)N_NODES * DIM];
__device__ float g_h[(size_t)N_NODES * DIM];
__device__ float g_W0[256 * 128];
__device__ float g_W12[256 * 128];
__device__ float g_b12[128];

// ---------------- CSR build ----------------
__global__ void zero_deg_kernel() {
    int i = blockIdx.x * blockDim.x + threadIdx.x;
    if (i < N_NODES) g_deg[i] = 0;
}

__global__ void degree_kernel(const int* __restrict__ dst) {
    int e = blockIdx.x * blockDim.x + threadIdx.x;
    if (e < N_EDGES) atomicAdd(&g_deg[dst[e]], 1);
}

// ---- decoupled 3-phase scan (49 blocks x 2048 elems) ----
__global__ void scan1_kernel() {      // per-block local exclusive scan + block totals
    __shared__ int wsum[32];
    const int tid = threadIdx.x;                 // 1024
    const int lane = tid & 31, wid = tid >> 5;
    const int base = blockIdx.x * SCAN_BLK;
    const int i0 = base + 2 * tid, i1 = i0 + 1;
    int v0 = (i0 < N_NODES) ? g_deg[i0] : 0;
    int v1 = (i1 < N_NODES) ? g_deg[i1] : 0;
    int s = v0 + v1;
    int x = s;
    #pragma unroll
    for (int d = 1; d < 32; d <<= 1) {
        int y = __shfl_up_sync(0xffffffffu, x, d);
        if (lane >= d) x += y;
    }
    if (lane == 31) wsum[wid] = x;
    __syncthreads();
    if (wid == 0) {
        int t = wsum[lane];
        #pragma unroll
        for (int d = 1; d < 32; d <<= 1) {
            int y = __shfl_up_sync(0xffffffffu, t, d);
            if (lane >= d) t += y;
        }
        wsum[lane] = t;
    }
    __syncthreads();
    int excl = (wid ? wsum[wid - 1] : 0) + x - s;   // exclusive prefix of this thread's pair
    if (i0 < N_NODES) g_off[i0] = excl;
    if (i1 < N_NODES) g_off[i1] = excl + v0;
    if (tid == 0) g_blk[blockIdx.x] = wsum[31];      // block total
}

__global__ void scan2_kernel() {      // tiny exclusive scan of 49 block totals
    __shared__ int sh[SCAN_NBLK];
    int tid = threadIdx.x;            // 64
    if (tid < SCAN_NBLK) sh[tid] = g_blk[tid];
    __syncthreads();
    if (tid == 0) {
        int run = 0;
        #pragma unroll 1
        for (int b = 0; b < SCAN_NBLK; b++) { int t = sh[b]; sh[b] = run; run += t; }
        g_off[N_NODES] = run;
    }
    __syncthreads();
    if (tid < SCAN_NBLK) g_blk[tid] = sh[tid];
}

__global__ void scan3_kernel() {      // add block offsets, init cursors
    int i = blockIdx.x * blockDim.x + threadIdx.x;
    if (i < N_NODES) {
        int o = g_off[i] + g_blk[i / SCAN_BLK];
        g_off[i] = o;
        g_cur[i] = o;
    }
}

__global__ void fill_kernel(const int* __restrict__ src, const int* __restrict__ dst) {
    int e = blockIdx.x * blockDim.x + threadIdx.x;
    if (e < N_EDGES) {
        int p = atomicAdd(&g_cur[dst[e]], 1);
        g_csr[p] = src[e];
    }
}

// ---------------- aggregation: one warp per node, mean over in-edges ----------------
template <int PHASE>
__global__ void agg_kernel(const float* __restrict__ xin) {
    const float* __restrict__ x = (PHASE == 0) ? xin : g_h;
    int w = (blockIdx.x * blockDim.x + threadIdx.x) >> 5;
    int lane = threadIdx.x & 31;
    if (w >= N_NODES) return;
    int beg = g_off[w], end = g_off[w + 1];
    float4 acc = make_float4(0.f, 0.f, 0.f, 0.f);
    int i = beg;
    for (; i + 4 <= end; i += 4) {
        int s0 = g_csr[i], s1 = g_csr[i + 1], s2 = g_csr[i + 2], s3 = g_csr[i + 3];
        float4 v0 = *((const float4*)(x + (size_t)s0 * DIM) + lane);
        float4 v1 = *((const float4*)(x + (size_t)s1 * DIM) + lane);
        float4 v2 = *((const float4*)(x + (size_t)s2 * DIM) + lane);
        float4 v3 = *((const float4*)(x + (size_t)s3 * DIM) + lane);
        acc.x += v0.x + v1.x + v2.x + v3.x;
        acc.y += v0.y + v1.y + v2.y + v3.y;
        acc.z += v0.z + v1.z + v2.z + v3.z;
        acc.w += v0.w + v1.w + v2.w + v3.w;
    }
    for (; i < end; i++) {
        int s = g_csr[i];
        float4 v = *((const float4*)(x + (size_t)s * DIM) + lane);
        acc.x += v.x; acc.y += v.y; acc.z += v.z; acc.w += v.w;
    }
    float inv = (end > beg) ? 1.0f / (float)(end - beg) : 0.0f;
    acc.x *= inv; acc.y *= inv; acc.z *= inv; acc.w *= inv;
    *((float4*)(g_agg + (size_t)w * DIM) + lane) = acc;
}

// ---------------- weight prep ----------------
__global__ void prep_weights(const float* __restrict__ ws0, const float* __restrict__ wn0,
                             const float* __restrict__ ws1, const float* __restrict__ wn1,
                             const float* __restrict__ ws2, const float* __restrict__ wn2,
                             const float* __restrict__ b1,  const float* __restrict__ b2) {
    int idx = blockIdx.x * blockDim.x + threadIdx.x;
    if (idx >= 256 * 128) return;
    int k = idx >> 7, j = idx & 127;
    g_W0[idx] = (k < 128) ? ws0[k * 128 + j] : wn0[(k - 128) * 128 + j];
    int g = j >> 3, w = j & 7;
    int m = g * 4 + (w & 3);
    int kk = k & 127;
    const float* Wsel;
    if (k < 128) Wsel = (w < 4) ? ws1 : ws2;
    else         Wsel = (w < 4) ? wn1 : wn2;
    g_W12[idx] = Wsel[kk * 64 + m];
    if (idx < 128) {
        int gg = idx >> 3, ww = idx & 7;
        int mm = gg * 4 + (ww & 3);
        g_b12[idx] = (ww < 4) ? b1[mm] : b2[mm];
    }
}

// ---------------- packed f32x2 helpers ----------------
__device__ __forceinline__ unsigned long long pack2(float lo, float hi) {
    unsigned long long p;
    asm("mov.b64 %0, {%1, %2};" : "=l"(p) : "f"(lo), "f"(hi));
    return p;
}
__device__ __forceinline__ void unpack2(unsigned long long p, float& lo, float& hi) {
    asm("mov.b64 {%0, %1}, %2;" : "=f"(lo), "=f"(hi) : "l"(p));
}
__device__ __forceinline__ void fma2(unsigned long long& d, unsigned long long a, unsigned long long b) {
    asm("fma.rn.f32x2 %0, %1, %2, %0;" : "+l"(d) : "l"(a), "l"(b));
}

// ---------------- fused dual-input GEMM (packed fp32x2 inner loop) ----------------
// Accumulators paired over ROWS: acc2[i2][j] holds rows {ty*8+2*i2, ty*8+2*i2+1}, col tx*8+j.
// MODE 0: h = relu(features @ Ws0 + agg @ Wn0 + b0)          -> g_h   [N,128]
// MODE 1: out = mean + noise*exp(log_std), cols interleaved  -> d_out [N,64]
template <int MODE>
__global__ void __launch_bounds__(256, 2)
gemm_kernel(const float* __restrict__ A0in, const float* __restrict__ bias,
            const float* __restrict__ noise, float* __restrict__ outp) {
    const float* __restrict__ A0 = (MODE == 0) ? A0in : g_h;
    const float* __restrict__ A1 = g_agg;
    const float* __restrict__ W  = (MODE == 0) ? g_W0 : g_W12;
    __shared__ float sA[16][128];   // [k][row]
    __shared__ float sB[16][128];   // [k][col]
    const int row0 = blockIdx.x * 128;
    const int t = threadIdx.x;
    const int tx = t & 15, ty = t >> 4;

    unsigned long long acc2[4][8];
    #pragma unroll
    for (int i = 0; i < 4; i++)
        #pragma unroll
        for (int j = 0; j < 8; j++) acc2[i][j] = 0ull;

    for (int k0 = 0; k0 < 256; k0 += 16) {
        const float* A = (k0 < 128) ? A0 : A1;
        const int kb = k0 & 127;
        #pragma unroll
        for (int i = 0; i < 2; i++) {
            int idx = t + i * 256;          // float4 index 0..511
            int r = idx >> 2, c4 = idx & 3;
            float4 v = make_float4(0.f, 0.f, 0.f, 0.f);
            int grow = row0 + r;
            if (grow < N_NODES) v = *(const float4*)(A + (size_t)grow * 128 + kb + c4 * 4);
            sA[c4 * 4 + 0][r] = v.x;
            sA[c4 * 4 + 1][r] = v.y;
            sA[c4 * 4 + 2][r] = v.z;
            sA[c4 * 4 + 3][r] = v.w;
        }
        #pragma unroll
        for (int i = 0; i < 2; i++) {
            int idx = t + i * 256;
            int r = idx >> 5, c4 = idx & 31;
            *(float4*)&sB[r][c4 * 4] = *(const float4*)(W + (size_t)(k0 + r) * 128 + c4 * 4);
        }
        __syncthreads();
        #pragma unroll
        for (int k = 0; k < 16; k++) {
            float a[8], bb[8];
            *(float4*)&a[0]  = *(const float4*)&sA[k][ty * 8];
            *(float4*)&a[4]  = *(const float4*)&sA[k][ty * 8 + 4];
            *(float4*)&bb[0] = *(const float4*)&sB[k][tx * 8];
            *(float4*)&bb[4] = *(const float4*)&sB[k][tx * 8 + 4];
            unsigned long long ap[4], bsp[8];
            #pragma unroll
            for (int i = 0; i < 4; i++) ap[i] = pack2(a[2 * i], a[2 * i + 1]);
            #pragma unroll
            for (int j = 0; j < 8; j++) bsp[j] = pack2(bb[j], bb[j]);
            #pragma unroll
            for (int i = 0; i < 4; i++)
                #pragma unroll
                for (int j = 0; j < 8; j++)
                    fma2(acc2[i][j], ap[i], bsp[j]);
        }
        __syncthreads();
    }

    if (MODE == 0) {
        #pragma unroll
        for (int i = 0; i < 4; i++) {
            int grow0 = row0 + ty * 8 + 2 * i;
            int grow1 = grow0 + 1;
            #pragma unroll
            for (int j = 0; j < 8; j++) {
                int col = tx * 8 + j;
                float lo, hi;
                unpack2(acc2[i][j], lo, hi);
                if (grow0 < N_NODES) g_h[(size_t)grow0 * 128 + col] = fmaxf(lo + bias[col], 0.f);
                if (grow1 < N_NODES) g_h[(size_t)grow1 * 128 + col] = fmaxf(hi + bias[col], 0.f);
            }
        }
    } else {
        #pragma unroll
        for (int i = 0; i < 4; i++) {
            int grow0 = row0 + ty * 8 + 2 * i;
            int grow1 = grow0 + 1;
            #pragma unroll
            for (int j = 0; j < 4; j++) {
                int oc = tx * 4 + j;
                float m_lo, m_hi, l_lo, l_hi;
                unpack2(acc2[i][j],     m_lo, m_hi);
                unpack2(acc2[i][j + 4], l_lo, l_hi);
                float bm = g_b12[tx * 8 + j];
                float bl = g_b12[tx * 8 + 4 + j];
                if (grow0 < N_NODES)
                    outp[(size_t)grow0 * 64 + oc] =
                        fmaf(noise[(size_t)grow0 * 64 + oc], expf(l_lo + bl), m_lo + bm);
                if (grow1 < N_NODES)
                    outp[(size_t)grow1 * 64 + oc] =
                        fmaf(noise[(size_t)grow1 * 64 + oc], expf(l_hi + bl), m_hi + bm);
            }
        }
    }
}

// ---------------- launch: pure kernel launches ----------------
extern "C" void kernel_launch(void* const* d_in, const int* in_sizes, int n_in,
                              void* d_out, int out_size) {
    const float* features = (const float*)d_in[0];
    const int*   src      = (const int*)  d_in[1];
    const int*   dst      = (const int*)  d_in[2];
    const float* noise    = (const float*)d_in[3];
    const float* ws0      = (const float*)d_in[4];
    const float* wn0      = (const float*)d_in[5];
    const float* b0       = (const float*)d_in[6];
    const float* ws1      = (const float*)d_in[7];
    const float* wn1      = (const float*)d_in[8];
    const float* b1       = (const float*)d_in[9];
    const float* ws2      = (const float*)d_in[10];
    const float* wn2      = (const float*)d_in[11];
    const float* b2       = (const float*)d_in[12];
    float* out = (float*)d_out;

    const int EB = N_EDGES / 256;              // 6250, exact
    const int GEMM_BLOCKS = (N_NODES + 127) / 128;
    const int AGG_BLOCKS  = (N_NODES * 32 + 255) / 256;

    zero_deg_kernel<<<(N_NODES + 255) / 256, 256>>>();
    prep_weights<<<128, 256>>>(ws0, wn0, ws1, wn1, ws2, wn2, b1, b2);
    degree_kernel<<<EB, 256>>>(dst);
    scan1_kernel<<<SCAN_NBLK, 1024>>>();
    scan2_kernel<<<1, 64>>>();
    scan3_kernel<<<(N_NODES + 255) / 256, 256>>>();
    fill_kernel<<<EB, 256>>>(src, dst);

    // layer 0
    agg_kernel<0><<<AGG_BLOCKS, 256>>>(features);
    gemm_kernel<0><<<GEMM_BLOCKS, 256>>>(features, b0, nullptr, nullptr);

    // layers 1 & 2 fused (one aggregation of h serves both mean and log_std)
    agg_kernel<1><<<AGG_BLOCKS, 256>>>(nullptr);
    gemm_kernel<1><<<GEMM_BLOCKS, 256>>>(nullptr, nullptr, noise, out);
}

// round 8
// speedup vs baseline: 1.9536x; 1.7483x over previous
#include <cuda_runtime.h>
#include <cuda_bf16.h>
#include <math.h>
#include <stdint.h>

#define N_NODES 100000
#define N_EDGES 1600000
#define DIM 128
#define SCAN_BLK 2048
#define SCAN_NBLK ((N_NODES + SCAN_BLK - 1) / SCAN_BLK)   // 49
#define GEMM_BLOCKS ((N_NODES + 127) / 128)               // 782

// smem layout for the MMA GEMM (static, < 48KB)
#define SA_STRIDE_B 80                     // 40 bf16 els (32 used + 8 pad), 16B-mult, conflict-free
#define SB_STRIDE_B 272                    // 136 bf16 els (128 used + 8 pad)
#define SM_SA_HI 0
#define SM_SA_LO (128 * SA_STRIDE_B)                       // 10240
#define SM_SB_HI (2 * 128 * SA_STRIDE_B)                   // 20480
#define SM_SB_LO (SM_SB_HI + 32 * SB_STRIDE_B)             // 29184
#define SM_TOTAL (SM_SB_LO + 32 * SB_STRIDE_B)             // 37888

// ---------------- scratch (no allocations allowed) ----------------
__device__ int   g_deg[N_NODES];
__device__ int   g_off[N_NODES + 1];
__device__ int   g_cur[N_NODES];
__device__ int   g_blk[SCAN_NBLK];
__device__ int   g_csr[N_EDGES];
__device__ float g_agg[(size_t)N_NODES * DIM];
__device__ float g_h[(size_t)N_NODES * DIM];
// Pre-split (hi/lo bf16), pre-transposed, padded B images: [which][k-half][hi/lo][128 rows(k) x 136(n)]
__device__ __nv_bfloat16 g_Bimg[2][2][2][128 * 136];
__device__ float g_bias12[128];   // [0:64) b1 (mean), [64:128) b2 (log_std)

// ---------------- CSR build ----------------
__global__ void zero_deg_kernel() {
    int i = blockIdx.x * blockDim.x + threadIdx.x;
    if (i < N_NODES) g_deg[i] = 0;
}
__global__ void degree_kernel(const int* __restrict__ dst) {
    int e = blockIdx.x * blockDim.x + threadIdx.x;
    if (e < N_EDGES) atomicAdd(&g_deg[dst[e]], 1);
}
__global__ void scan1_kernel() {
    __shared__ int wsum[32];
    const int tid = threadIdx.x;
    const int lane = tid & 31, wid = tid >> 5;
    const int base = blockIdx.x * SCAN_BLK;
    const int i0 = base + 2 * tid, i1 = i0 + 1;
    int v0 = (i0 < N_NODES) ? g_deg[i0] : 0;
    int v1 = (i1 < N_NODES) ? g_deg[i1] : 0;
    int s = v0 + v1;
    int x = s;
    #pragma unroll
    for (int d = 1; d < 32; d <<= 1) {
        int y = __shfl_up_sync(0xffffffffu, x, d);
        if (lane >= d) x += y;
    }
    if (lane == 31) wsum[wid] = x;
    __syncthreads();
    if (wid == 0) {
        int t = wsum[lane];
        #pragma unroll
        for (int d = 1; d < 32; d <<= 1) {
            int y = __shfl_up_sync(0xffffffffu, t, d);
            if (lane >= d) t += y;
        }
        wsum[lane] = t;
    }
    __syncthreads();
    int excl = (wid ? wsum[wid - 1] : 0) + x - s;
    if (i0 < N_NODES) g_off[i0] = excl;
    if (i1 < N_NODES) g_off[i1] = excl + v0;
    if (tid == 0) g_blk[blockIdx.x] = wsum[31];
}
__global__ void scan2_kernel() {
    __shared__ int sh[SCAN_NBLK];
    int tid = threadIdx.x;
    if (tid < SCAN_NBLK) sh[tid] = g_blk[tid];
    __syncthreads();
    if (tid == 0) {
        int run = 0;
        #pragma unroll 1
        for (int b = 0; b < SCAN_NBLK; b++) { int t = sh[b]; sh[b] = run; run += t; }
        g_off[N_NODES] = run;
    }
    __syncthreads();
    if (tid < SCAN_NBLK) g_blk[tid] = sh[tid];
}
__global__ void scan3_kernel() {
    int i = blockIdx.x * blockDim.x + threadIdx.x;
    if (i < N_NODES) {
        int o = g_off[i] + g_blk[i / SCAN_BLK];
        g_off[i] = o;
        g_cur[i] = o;
    }
}
__global__ void fill_kernel(const int* __restrict__ src, const int* __restrict__ dst) {
    int e = blockIdx.x * blockDim.x + threadIdx.x;
    if (e < N_EDGES) {
        int p = atomicAdd(&g_cur[dst[e]], 1);
        g_csr[p] = src[e];
    }
}

// ---------------- aggregation: one warp per node, mean over in-edges ----------------
template <int PHASE>
__global__ void agg_kernel(const float* __restrict__ xin) {
    const float* __restrict__ x = (PHASE == 0) ? xin : g_h;
    int w = (blockIdx.x * blockDim.x + threadIdx.x) >> 5;
    int lane = threadIdx.x & 31;
    if (w >= N_NODES) return;
    int beg = g_off[w], end = g_off[w + 1];
    float4 acc = make_float4(0.f, 0.f, 0.f, 0.f);
    int i = beg;
    for (; i + 4 <= end; i += 4) {
        int s0 = g_csr[i], s1 = g_csr[i + 1], s2 = g_csr[i + 2], s3 = g_csr[i + 3];
        float4 v0 = *((const float4*)(x + (size_t)s0 * DIM) + lane);
        float4 v1 = *((const float4*)(x + (size_t)s1 * DIM) + lane);
        float4 v2 = *((const float4*)(x + (size_t)s2 * DIM) + lane);
        float4 v3 = *((const float4*)(x + (size_t)s3 * DIM) + lane);
        acc.x += v0.x + v1.x + v2.x + v3.x;
        acc.y += v0.y + v1.y + v2.y + v3.y;
        acc.z += v0.z + v1.z + v2.z + v3.z;
        acc.w += v0.w + v1.w + v2.w + v3.w;
    }
    for (; i < end; i++) {
        int s = g_csr[i];
        float4 v = *((const float4*)(x + (size_t)s * DIM) + lane);
        acc.x += v.x; acc.y += v.y; acc.z += v.z; acc.w += v.w;
    }
    float inv = (end > beg) ? 1.0f / (float)(end - beg) : 0.0f;
    acc.x *= inv; acc.y *= inv; acc.z *= inv; acc.w *= inv;
    *((float4*)(g_agg + (size_t)w * DIM) + lane) = acc;
}

// ---------------- weight prep: transpose + bf16 hi/lo split into padded B images ----------------
// W0 image: col j = output col. W12 image: n-tile interleave (even n8-tile = mean, odd = log_std).
__global__ void prep_weights(const float* __restrict__ ws0, const float* __restrict__ wn0,
                             const float* __restrict__ ws1, const float* __restrict__ wn1,
                             const float* __restrict__ ws2, const float* __restrict__ wn2,
                             const float* __restrict__ b1,  const float* __restrict__ b2) {
    int idx = blockIdx.x * blockDim.x + threadIdx.x;   // 0..65535
    if (idx < 128) g_bias12[idx] = (idx < 64) ? b1[idx] : b2[idx - 64];
    if (idx >= 65536) return;
    int which = idx >> 15;            // 0: layer0 W, 1: layers1&2 W
    int half  = (idx >> 14) & 1;      // 0: self, 1: neigh
    int k = (idx >> 7) & 127;
    int j = idx & 127;
    float v;
    if (which == 0) {
        v = (half ? wn0 : ws0)[k * 128 + j];
    } else {
        int nt = j >> 3, jin = j & 7;
        int sel = nt & 1;                       // 0: mean (w1), 1: log_std (w2)
        int oc = (nt >> 1) * 8 + jin;           // 0..63
        const float* W = sel ? (half ? wn2 : ws2) : (half ? wn1 : ws1);
        v = W[k * 64 + oc];
    }
    __nv_bfloat16 hi = __float2bfloat16(v);
    __nv_bfloat16 lo = __float2bfloat16(v - __bfloat162float(hi));
    g_Bimg[which][half][0][k * 136 + j] = hi;
    g_Bimg[which][half][1][k * 136 + j] = lo;
}

// ---------------- mma.sync helpers ----------------
__device__ __forceinline__ uint32_t smem_u32(const void* p) {
    uint32_t a;
    asm("{ .reg .u64 t; cvta.to.shared.u64 t, %1; cvt.u32.u64 %0, t; }" : "=r"(a) : "l"(p));
    return a;
}
__device__ __forceinline__ void ldsm4(uint32_t* r, uint32_t addr) {
    asm volatile("ldmatrix.sync.aligned.m8n8.x4.shared.b16 {%0,%1,%2,%3}, [%4];"
                 : "=r"(r[0]), "=r"(r[1]), "=r"(r[2]), "=r"(r[3]) : "r"(addr));
}
__device__ __forceinline__ void ldsm4t(uint32_t* r, uint32_t addr) {
    asm volatile("ldmatrix.sync.aligned.m8n8.x4.trans.shared.b16 {%0,%1,%2,%3}, [%4];"
                 : "=r"(r[0]), "=r"(r[1]), "=r"(r[2]), "=r"(r[3]) : "r"(addr));
}
__device__ __forceinline__ void mma16816(float* c, const uint32_t* a, uint32_t b0, uint32_t b1) {
    asm volatile("mma.sync.aligned.m16n8k16.row.col.f32.bf16.bf16.f32 "
                 "{%0,%1,%2,%3}, {%4,%5,%6,%7}, {%8,%9}, {%0,%1,%2,%3};"
                 : "+f"(c[0]), "+f"(c[1]), "+f"(c[2]), "+f"(c[3])
                 : "r"(a[0]), "r"(a[1]), "r"(a[2]), "r"(a[3]), "r"(b0), "r"(b1));
}
__device__ __forceinline__ uint32_t pack_bf2(float x, float y) {
    __nv_bfloat162 h = __floats2bfloat162_rn(x, y);   // x -> low, y -> high
    return *(uint32_t*)&h;
}

// ---------------- HMMA GEMM with 3xBF16 split ----------------
// C[128t,128] = A[128t,256] @ W[256,128];  A = [X | agg] (two 128-k halves)
// MODE 0: g_h = relu(C + b0)
// MODE 1: out[r,oc] = (C_mean + b1) + noise * exp(C_ls + b2); mean/ls interleaved per n8-tile
template <int MODE>
__global__ void __launch_bounds__(256, 2)
mma_gemm_kernel(const float* __restrict__ A0in, const float* __restrict__ bias0,
                const float* __restrict__ noise, float* __restrict__ outp) {
    __shared__ __align__(16) char smem[SM_TOTAL];
    const uint32_t sb = smem_u32(smem);
    const int t = threadIdx.x;
    const int lane = t & 31, wid = t >> 5;
    const int wm = wid & 3, wn = wid >> 2;        // warp grid 4(m) x 2(n)
    const int row0 = blockIdx.x * 128;
    const int gid = lane >> 2, tig = lane & 3;

    float acc[2][8][4];
    #pragma unroll
    for (int m = 0; m < 2; m++)
        #pragma unroll
        for (int n = 0; n < 8; n++)
            #pragma unroll
            for (int q = 0; q < 4; q++) acc[m][n][q] = 0.f;

    // ldmatrix lane address components
    const int a_row  = lane & 15;
    const int a_kcol = (lane >> 4) * 8;
    const int b_krow = ((lane >> 3) & 1) * 8 + (lane & 7);
    const int b_ncol = (lane >> 4) * 8;

    const int ldrow = t >> 1;               // A-load: 2 threads per row
    const int ldk   = (t & 1) * 16;

    #pragma unroll 1
    for (int c = 0; c < 8; c++) {           // 8 k-chunks of 32 (2 halves x 4)
        const int half = c >> 2;
        const int kb = (c & 3) * 32;
        const float* Asrc = half ? g_agg : (MODE == 0 ? A0in : g_h);

        // ---- A: load 128x32 fp32, split hi/lo bf16, store padded ----
        {
            const int grow = row0 + ldrow;
            const uint32_t sa = sb + ldrow * SA_STRIDE_B + ldk * 2;
            #pragma unroll
            for (int i = 0; i < 4; i++) {
                float4 v = make_float4(0.f, 0.f, 0.f, 0.f);
                if (grow < N_NODES)
                    v = *(const float4*)(Asrc + (size_t)grow * 128 + kb + ldk + i * 4);
                __nv_bfloat16 h0 = __float2bfloat16(v.x), h1 = __float2bfloat16(v.y);
                __nv_bfloat16 h2 = __float2bfloat16(v.z), h3 = __float2bfloat16(v.w);
                uint32_t hi01 = pack_bf2(__bfloat162float(h0), __bfloat162float(h1));
                uint32_t hi23 = pack_bf2(__bfloat162float(h2), __bfloat162float(h3));
                uint32_t lo01 = pack_bf2(v.x - __bfloat162float(h0), v.y - __bfloat162float(h1));
                uint32_t lo23 = pack_bf2(v.z - __bfloat162float(h2), v.w - __bfloat162float(h3));
                uint32_t off = sa + i * 8;
                asm volatile("st.shared.v2.b32 [%0], {%1,%2};" :: "r"(off + SM_SA_HI), "r"(hi01), "r"(hi23));
                asm volatile("st.shared.v2.b32 [%0], {%1,%2};" :: "r"(off + SM_SA_LO), "r"(lo01), "r"(lo23));
            }
        }
        // ---- B: straight copy of prebuilt padded images (32 rows x 272B, hi+lo) ----
        {
            const uint4* bh = (const uint4*)&g_Bimg[MODE][half][0][(c & 3) * 32 * 136];
            const uint4* bl = (const uint4*)&g_Bimg[MODE][half][1][(c & 3) * 32 * 136];
            uint4* sh_ = (uint4*)(smem + SM_SB_HI);
            uint4* sl_ = (uint4*)(smem + SM_SB_LO);
            #pragma unroll
            for (int i = 0; i < 3; i++) {
                int ix = t + i * 256;
                if (ix < 544) { sh_[ix] = bh[ix]; sl_[ix] = bl[ix]; }
            }
        }
        __syncthreads();

        // ---- 2 k16 steps of fragment loads + mma ----
        #pragma unroll
        for (int ks = 0; ks < 2; ks++) {
            const int k16 = ks * 16;
            uint32_t ahi[2][4], alo[2][4];
            #pragma unroll
            for (int m = 0; m < 2; m++) {
                uint32_t aaddr = sb + (wm * 32 + m * 16 + a_row) * SA_STRIDE_B + (k16 + a_kcol) * 2;
                ldsm4(ahi[m], aaddr + SM_SA_HI);
                ldsm4(alo[m], aaddr + SM_SA_LO);
            }
            #pragma unroll
            for (int np = 0; np < 4; np++) {
                uint32_t baddr = sb + SM_SB_HI + (k16 + b_krow) * SB_STRIDE_B
                               + (wn * 64 + np * 16 + b_ncol) * 2;
                uint32_t bh[4], bl[4];
                ldsm4t(bh, baddr);
                ldsm4t(bl, baddr + (SM_SB_LO - SM_SB_HI));
                #pragma unroll
                for (int m = 0; m < 2; m++) {
                    #pragma unroll
                    for (int nn = 0; nn < 2; nn++) {
                        float* a_ = acc[m][np * 2 + nn];
                        mma16816(a_, ahi[m], bh[nn * 2], bh[nn * 2 + 1]);
                        mma16816(a_, ahi[m], bl[nn * 2], bl[nn * 2 + 1]);
                        mma16816(a_, alo[m], bh[nn * 2], bh[nn * 2 + 1]);
                    }
                }
            }
        }
        __syncthreads();
    }

    // ---- epilogue ----
    #pragma unroll
    for (int m = 0; m < 2; m++) {
        const int r = row0 + wm * 32 + m * 16 + gid;
        if (MODE == 0) {
            #pragma unroll
            for (int nt = 0; nt < 8; nt++) {
                const int col = wn * 64 + nt * 8 + tig * 2;
                float ba = bias0[col], bb = bias0[col + 1];
                if (r < N_NODES) {
                    float2 o = make_float2(fmaxf(acc[m][nt][0] + ba, 0.f),
                                           fmaxf(acc[m][nt][1] + bb, 0.f));
                    *(float2*)(g_h + (size_t)r * 128 + col) = o;
                }
                if (r + 8 < N_NODES) {
                    float2 o = make_float2(fmaxf(acc[m][nt][2] + ba, 0.f),
                                           fmaxf(acc[m][nt][3] + bb, 0.f));
                    *(float2*)(g_h + (size_t)(r + 8) * 128 + col) = o;
                }
            }
        } else {
            #pragma unroll
            for (int q = 0; q < 4; q++) {
                const int oc = (wn * 4 + q) * 8 + tig * 2;
                const float* am = acc[m][2 * q];       // mean tile
                const float* al = acc[m][2 * q + 1];   // log_std tile
                float bm0 = g_bias12[oc], bm1 = g_bias12[oc + 1];
                float bl0 = g_bias12[64 + oc], bl1 = g_bias12[64 + oc + 1];
                if (r < N_NODES) {
                    float2 nz = *(const float2*)(noise + (size_t)r * 64 + oc);
                    float2 o = make_float2(fmaf(nz.x, expf(al[0] + bl0), am[0] + bm0),
                                           fmaf(nz.y, expf(al[1] + bl1), am[1] + bm1));
                    *(float2*)(outp + (size_t)r * 64 + oc) = o;
                }
                if (r + 8 < N_NODES) {
                    float2 nz = *(const float2*)(noise + (size_t)(r + 8) * 64 + oc);
                    float2 o = make_float2(fmaf(nz.x, expf(al[2] + bl0), am[2] + bm0),
                                           fmaf(nz.y, expf(al[3] + bl1), am[3] + bm1));
                    *(float2*)(outp + (size_t)(r + 8) * 64 + oc) = o;
                }
            }
        }
    }
}

// ---------------- launch: pure kernel launches ----------------
extern "C" void kernel_launch(void* const* d_in, const int* in_sizes, int n_in,
                              void* d_out, int out_size) {
    const float* features = (const float*)d_in[0];
    const int*   src      = (const int*)  d_in[1];
    const int*   dst      = (const int*)  d_in[2];
    const float* noise    = (const float*)d_in[3];
    const float* ws0      = (const float*)d_in[4];
    const float* wn0      = (const float*)d_in[5];
    const float* b0       = (const float*)d_in[6];
    const float* ws1      = (const float*)d_in[7];
    const float* wn1      = (const float*)d_in[8];
    const float* b1       = (const float*)d_in[9];
    const float* ws2      = (const float*)d_in[10];
    const float* wn2      = (const float*)d_in[11];
    const float* b2       = (const float*)d_in[12];
    float* out = (float*)d_out;

    const int EB = N_EDGES / 256;              // 6250, exact
    const int AGG_BLOCKS = (N_NODES * 32 + 255) / 256;

    zero_deg_kernel<<<(N_NODES + 255) / 256, 256>>>();
    prep_weights<<<256, 256>>>(ws0, wn0, ws1, wn1, ws2, wn2, b1, b2);
    degree_kernel<<<EB, 256>>>(dst);
    scan1_kernel<<<SCAN_NBLK, 1024>>>();
    scan2_kernel<<<1, 64>>>();
    scan3_kernel<<<(N_NODES + 255) / 256, 256>>>();
    fill_kernel<<<EB, 256>>>(src, dst);

    // layer 0
    agg_kernel<0><<<AGG_BLOCKS, 256>>>(features);
    mma_gemm_kernel<0><<<GEMM_BLOCKS, 256>>>(features, b0, nullptr, nullptr);

    // layers 1 & 2 fused (one aggregation of h serves both mean and log_std)
    agg_kernel<1><<<AGG_BLOCKS, 256>>>(nullptr);
    mma_gemm_kernel<1><<<GEMM_BLOCKS, 256>>>(nullptr, nullptr, noise, out);
}

// round 11
// speedup vs baseline: 1.9669x; 1.0068x over previous
#include <cuda_runtime.h>
#include <cuda_bf16.h>
#include <cuda_fp16.h>
#include <math.h>
#include <stdint.h>

#define N_NODES 100000
#define N_EDGES 1600000
#define DIM 128
#define SCAN_BLK 2048
#define SCAN_NBLK ((N_NODES + SCAN_BLK - 1) / SCAN_BLK)   // 49
#define GEMM_BLOCKS ((N_NODES + 127) / 128)               // 782

// smem layout for the MMA GEMM (static, < 48KB)
#define SA_STRIDE_B 80
#define SB_STRIDE_B 272
#define SM_SA_HI 0
#define SM_SA_LO (128 * SA_STRIDE_B)
#define SM_SB_HI (2 * 128 * SA_STRIDE_B)
#define SM_SB_LO (SM_SB_HI + 32 * SB_STRIDE_B)
#define SM_TOTAL (SM_SB_LO + 32 * SB_STRIDE_B)            // 37888

// ---------------- scratch (no allocations allowed) ----------------
__device__ int    g_deg[N_NODES];
__device__ int    g_off[N_NODES + 1];
__device__ int    g_cur[N_NODES];
__device__ int    g_blk[SCAN_NBLK];
__device__ int    g_csr[N_EDGES];
__device__ float  g_agg[(size_t)N_NODES * DIM];
__device__ float  g_h[(size_t)N_NODES * DIM];
__device__ __half g_xh[(size_t)N_NODES * DIM];    // fp16 mirror: features, then h (reused)
__device__ __nv_bfloat16 g_Bimg[2][2][2][128 * 136];
__device__ float  g_bias12[128];

// ---------------- CSR build ----------------
__global__ void zero_deg_kernel() {
    int i = blockIdx.x * blockDim.x + threadIdx.x;
    if (i < N_NODES) g_deg[i] = 0;
}
__global__ void degree_kernel(const int* __restrict__ dst) {
    int e = blockIdx.x * blockDim.x + threadIdx.x;
    if (e < N_EDGES) atomicAdd(&g_deg[dst[e]], 1);
}
__global__ void scan1_kernel() {
    __shared__ int wsum[32];
    const int tid = threadIdx.x;
    const int lane = tid & 31, wid = tid >> 5;
    const int base = blockIdx.x * SCAN_BLK;
    const int i0 = base + 2 * tid, i1 = i0 + 1;
    int v0 = (i0 < N_NODES) ? g_deg[i0] : 0;
    int v1 = (i1 < N_NODES) ? g_deg[i1] : 0;
    int s = v0 + v1;
    int x = s;
    #pragma unroll
    for (int d = 1; d < 32; d <<= 1) {
        int y = __shfl_up_sync(0xffffffffu, x, d);
        if (lane >= d) x += y;
    }
    if (lane == 31) wsum[wid] = x;
    __syncthreads();
    if (wid == 0) {
        int t = wsum[lane];
        #pragma unroll
        for (int d = 1; d < 32; d <<= 1) {
            int y = __shfl_up_sync(0xffffffffu, t, d);
            if (lane >= d) t += y;
        }
        wsum[lane] = t;
    }
    __syncthreads();
    int excl = (wid ? wsum[wid - 1] : 0) + x - s;
    if (i0 < N_NODES) g_off[i0] = excl;
    if (i1 < N_NODES) g_off[i1] = excl + v0;
    if (tid == 0) g_blk[blockIdx.x] = wsum[31];
}
__global__ void scan2_kernel() {
    __shared__ int sh[SCAN_NBLK];
    int tid = threadIdx.x;
    if (tid < SCAN_NBLK) sh[tid] = g_blk[tid];
    __syncthreads();
    if (tid == 0) {
        int run = 0;
        #pragma unroll 1
        for (int b = 0; b < SCAN_NBLK; b++) { int t = sh[b]; sh[b] = run; run += t; }
        g_off[N_NODES] = run;
    }
    __syncthreads();
    if (tid < SCAN_NBLK) g_blk[tid] = sh[tid];
}
__global__ void scan3_kernel() {
    int i = blockIdx.x * blockDim.x + threadIdx.x;
    if (i < N_NODES) {
        int o = g_off[i] + g_blk[i / SCAN_BLK];
        g_off[i] = o;
        g_cur[i] = o;
    }
}
__global__ void fill_kernel(const int* __restrict__ src, const int* __restrict__ dst) {
    int e = blockIdx.x * blockDim.x + threadIdx.x;
    if (e < N_EDGES) {
        int p = atomicAdd(&g_cur[dst[e]], 1);
        g_csr[p] = src[e];
    }
}

// ---------------- fp32 -> fp16 mirror of features ----------------
__global__ void conv_kernel(const float* __restrict__ x) {
    int i = blockIdx.x * blockDim.x + threadIdx.x;   // float4 index, 3.2M total
    if (i < N_NODES * (DIM / 4)) {
        float4 v = ((const float4*)x)[i];
        __half2 a = __floats2half2_rn(v.x, v.y);
        __half2 b = __floats2half2_rn(v.z, v.w);
        uint2 u;
        u.x = *(uint32_t*)&a;
        u.y = *(uint32_t*)&b;
        *(uint2*)&g_xh[(size_t)i * 4] = u;
    }
}

// ---------------- aggregation: one warp per node, fp16 rows, fp32 accumulation ----------------
__global__ void agg_kernel() {
    int w = (blockIdx.x * blockDim.x + threadIdx.x) >> 5;
    int lane = threadIdx.x & 31;
    if (w >= N_NODES) return;
    int beg = g_off[w], end = g_off[w + 1];
    float4 acc = make_float4(0.f, 0.f, 0.f, 0.f);
    int i = beg;
    for (; i + 4 <= end; i += 4) {
        int s0 = g_csr[i], s1 = g_csr[i + 1], s2 = g_csr[i + 2], s3 = g_csr[i + 3];
        uint2 u0 = *((const uint2*)(g_xh + (size_t)s0 * DIM) + lane);
        uint2 u1 = *((const uint2*)(g_xh + (size_t)s1 * DIM) + lane);
        uint2 u2 = *((const uint2*)(g_xh + (size_t)s2 * DIM) + lane);
        uint2 u3 = *((const uint2*)(g_xh + (size_t)s3 * DIM) + lane);
        #pragma unroll
        for (int q = 0; q < 4; q++) {
            uint2 u = (q == 0) ? u0 : (q == 1) ? u1 : (q == 2) ? u2 : u3;
            float2 f0 = __half22float2(*(__half2*)&u.x);
            float2 f1 = __half22float2(*(__half2*)&u.y);
            acc.x += f0.x; acc.y += f0.y; acc.z += f1.x; acc.w += f1.y;
        }
    }
    for (; i < end; i++) {
        int s = g_csr[i];
        uint2 u = *((const uint2*)(g_xh + (size_t)s * DIM) + lane);
        float2 f0 = __half22float2(*(__half2*)&u.x);
        float2 f1 = __half22float2(*(__half2*)&u.y);
        acc.x += f0.x; acc.y += f0.y; acc.z += f1.x; acc.w += f1.y;
    }
    float inv = (end > beg) ? 1.0f / (float)(end - beg) : 0.0f;
    acc.x *= inv; acc.y *= inv; acc.z *= inv; acc.w *= inv;
    *((float4*)(g_agg + (size_t)w * DIM) + lane) = acc;
}

// ---------------- weight prep: transpose + bf16 hi/lo split into padded B images ----------------
__global__ void prep_weights(const float* __restrict__ ws0, const float* __restrict__ wn0,
                             const float* __restrict__ ws1, const float* __restrict__ wn1,
                             const float* __restrict__ ws2, const float* __restrict__ wn2,
                             const float* __restrict__ b1,  const float* __restrict__ b2) {
    int idx = blockIdx.x * blockDim.x + threadIdx.x;
    if (idx < 128) g_bias12[idx] = (idx < 64) ? b1[idx] : b2[idx - 64];
    if (idx >= 65536) return;
    int which = idx >> 15;
    int half  = (idx >> 14) & 1;
    int k = (idx >> 7) & 127;
    int j = idx & 127;
    float v;
    if (which == 0) {
        v = (half ? wn0 : ws0)[k * 128 + j];
    } else {
        int nt = j >> 3, jin = j & 7;
        int sel = nt & 1;
        int oc = (nt >> 1) * 8 + jin;
        const float* W = sel ? (half ? wn2 : ws2) : (half ? wn1 : ws1);
        v = W[k * 64 + oc];
    }
    __nv_bfloat16 hi = __float2bfloat16(v);
    __nv_bfloat16 lo = __float2bfloat16(v - __bfloat162float(hi));
    g_Bimg[which][half][0][k * 136 + j] = hi;
    g_Bimg[which][half][1][k * 136 + j] = lo;
}

// ---------------- mma.sync helpers ----------------
__device__ __forceinline__ uint32_t smem_u32(const void* p) {
    uint32_t a;
    asm("{ .reg .u64 t; cvta.to.shared.u64 t, %1; cvt.u32.u64 %0, t; }" : "=r"(a) : "l"(p));
    return a;
}
__device__ __forceinline__ void ldsm4(uint32_t* r, uint32_t addr) {
    asm volatile("ldmatrix.sync.aligned.m8n8.x4.shared.b16 {%0,%1,%2,%3}, [%4];"
                 : "=r"(r[0]), "=r"(r[1]), "=r"(r[2]), "=r"(r[3]) : "r"(addr));
}
__device__ __forceinline__ void ldsm4t(uint32_t* r, uint32_t addr) {
    asm volatile("ldmatrix.sync.aligned.m8n8.x4.trans.shared.b16 {%0,%1,%2,%3}, [%4];"
                 : "=r"(r[0]), "=r"(r[1]), "=r"(r[2]), "=r"(r[3]) : "r"(addr));
}
__device__ __forceinline__ void mma16816(float* c, const uint32_t* a, uint32_t b0, uint32_t b1) {
    asm volatile("mma.sync.aligned.m16n8k16.row.col.f32.bf16.bf16.f32 "
                 "{%0,%1,%2,%3}, {%4,%5,%6,%7}, {%8,%9}, {%0,%1,%2,%3};"
                 : "+f"(c[0]), "+f"(c[1]), "+f"(c[2]), "+f"(c[3])
                 : "r"(a[0]), "r"(a[1]), "r"(a[2]), "r"(a[3]), "r"(b0), "r"(b1));
}
__device__ __forceinline__ uint32_t pack_bf2(float x, float y) {
    __nv_bfloat162 h = __floats2bfloat162_rn(x, y);
    return *(uint32_t*)&h;
}

// ---------------- HMMA GEMM with 3xBF16 split ----------------
// MODE 0: g_h = relu(C + b0), also writes fp16 mirror g_xh
// MODE 1: out = (C_mean + b1) + noise * exp(C_ls + b2)
template <int MODE>
__global__ void __launch_bounds__(256, 2)
mma_gemm_kernel(const float* __restrict__ A0in, const float* __restrict__ bias0,
                const float* __restrict__ noise, float* __restrict__ outp) {
    __shared__ __align__(16) char smem[SM_TOTAL];
    const uint32_t sb = smem_u32(smem);
    const int t = threadIdx.x;
    const int lane = t & 31, wid = t >> 5;
    const int wm = wid & 3, wn = wid >> 2;
    const int row0 = blockIdx.x * 128;
    const int gid = lane >> 2, tig = lane & 3;

    float acc[2][8][4];
    #pragma unroll
    for (int m = 0; m < 2; m++)
        #pragma unroll
        for (int n = 0; n < 8; n++)
            #pragma unroll
            for (int q = 0; q < 4; q++) acc[m][n][q] = 0.f;

    const int a_row  = lane & 15;
    const int a_kcol = (lane >> 4) * 8;
    const int b_krow = ((lane >> 3) & 1) * 8 + (lane & 7);
    const int b_ncol = (lane >> 4) * 8;

    const int ldrow = t >> 1;
    const int ldk   = (t & 1) * 16;

    #pragma unroll 1
    for (int c = 0; c < 8; c++) {
        const int half = c >> 2;
        const int kb = (c & 3) * 32;
        const float* Asrc = half ? g_agg : (MODE == 0 ? A0in : g_h);

        {
            const int grow = row0 + ldrow;
            const uint32_t sa = sb + ldrow * SA_STRIDE_B + ldk * 2;
            #pragma unroll
            for (int i = 0; i < 4; i++) {
                float4 v = make_float4(0.f, 0.f, 0.f, 0.f);
                if (grow < N_NODES)
                    v = *(const float4*)(Asrc + (size_t)grow * 128 + kb + ldk + i * 4);
                __nv_bfloat16 h0 = __float2bfloat16(v.x), h1 = __float2bfloat16(v.y);
                __nv_bfloat16 h2 = __float2bfloat16(v.z), h3 = __float2bfloat16(v.w);
                uint32_t hi01 = pack_bf2(__bfloat162float(h0), __bfloat162float(h1));
                uint32_t hi23 = pack_bf2(__bfloat162float(h2), __bfloat162float(h3));
                uint32_t lo01 = pack_bf2(v.x - __bfloat162float(h0), v.y - __bfloat162float(h1));
                uint32_t lo23 = pack_bf2(v.z - __bfloat162float(h2), v.w - __bfloat162float(h3));
                uint32_t off = sa + i * 8;
                asm volatile("st.shared.v2.b32 [%0], {%1,%2};" :: "r"(off + SM_SA_HI), "r"(hi01), "r"(hi23));
                asm volatile("st.shared.v2.b32 [%0], {%1,%2};" :: "r"(off + SM_SA_LO), "r"(lo01), "r"(lo23));
            }
        }
        {
            const uint4* bh = (const uint4*)&g_Bimg[MODE][half][0][(c & 3) * 32 * 136];
            const uint4* bl = (const uint4*)&g_Bimg[MODE][half][1][(c & 3) * 32 * 136];
            uint4* sh_ = (uint4*)(smem + SM_SB_HI);
            uint4* sl_ = (uint4*)(smem + SM_SB_LO);
            #pragma unroll
            for (int i = 0; i < 3; i++) {
                int ix = t + i * 256;
                if (ix < 544) { sh_[ix] = bh[ix]; sl_[ix] = bl[ix]; }
            }
        }
        __syncthreads();

        #pragma unroll
        for (int ks = 0; ks < 2; ks++) {
            const int k16 = ks * 16;
            uint32_t ahi[2][4], alo[2][4];
            #pragma unroll
            for (int m = 0; m < 2; m++) {
                uint32_t aaddr = sb + (wm * 32 + m * 16 + a_row) * SA_STRIDE_B + (k16 + a_kcol) * 2;
                ldsm4(ahi[m], aaddr + SM_SA_HI);
                ldsm4(alo[m], aaddr + SM_SA_LO);
            }
            #pragma unroll
            for (int np = 0; np < 4; np++) {
                uint32_t baddr = sb + SM_SB_HI + (k16 + b_krow) * SB_STRIDE_B
                               + (wn * 64 + np * 16 + b_ncol) * 2;
                uint32_t bh[4], bl[4];
                ldsm4t(bh, baddr);
                ldsm4t(bl, baddr + (SM_SB_LO - SM_SB_HI));
                #pragma unroll
                for (int m = 0; m < 2; m++) {
                    #pragma unroll
                    for (int nn = 0; nn < 2; nn++) {
                        float* a_ = acc[m][np * 2 + nn];
                        mma16816(a_, ahi[m], bh[nn * 2], bh[nn * 2 + 1]);
                        mma16816(a_, ahi[m], bl[nn * 2], bl[nn * 2 + 1]);
                        mma16816(a_, alo[m], bh[nn * 2], bh[nn * 2 + 1]);
                    }
                }
            }
        }
        __syncthreads();
    }

    // ---- epilogue ----
    #pragma unroll
    for (int m = 0; m < 2; m++) {
        const int r = row0 + wm * 32 + m * 16 + gid;
        if (MODE == 0) {
            #pragma unroll
            for (int nt = 0; nt < 8; nt++) {
                const int col = wn * 64 + nt * 8 + tig * 2;
                float ba = bias0[col], bb = bias0[col + 1];
                if (r < N_NODES) {
                    float2 o = make_float2(fmaxf(acc[m][nt][0] + ba, 0.f),
                                           fmaxf(acc[m][nt][1] + bb, 0.f));
                    *(float2*)(g_h + (size_t)r * 128 + col) = o;
                    __half2 hh = __floats2half2_rn(o.x, o.y);
                    *(uint32_t*)&g_xh[(size_t)r * 128 + col] = *(uint32_t*)&hh;
                }
                if (r + 8 < N_NODES) {
                    float2 o = make_float2(fmaxf(acc[m][nt][2] + ba, 0.f),
                                           fmaxf(acc[m][nt][3] + bb, 0.f));
                    *(float2*)(g_h + (size_t)(r + 8) * 128 + col) = o;
                    __half2 hh = __floats2half2_rn(o.x, o.y);
                    *(uint32_t*)&g_xh[(size_t)(r + 8) * 128 + col] = *(uint32_t*)&hh;
                }
            }
        } else {
            #pragma unroll
            for (int q = 0; q < 4; q++) {
                const int oc = (wn * 4 + q) * 8 + tig * 2;
                const float* am = acc[m][2 * q];
                const float* al = acc[m][2 * q + 1];
                float bm0 = g_bias12[oc], bm1 = g_bias12[oc + 1];
                float bl0 = g_bias12[64 + oc], bl1 = g_bias12[64 + oc + 1];
                if (r < N_NODES) {
                    float2 nz = *(const float2*)(noise + (size_t)r * 64 + oc);
                    float2 o = make_float2(fmaf(nz.x, expf(al[0] + bl0), am[0] + bm0),
                                           fmaf(nz.y, expf(al[1] + bl1), am[1] + bm1));
                    *(float2*)(outp + (size_t)r * 64 + oc) = o;
                }
                if (r + 8 < N_NODES) {
                    float2 nz = *(const float2*)(noise + (size_t)(r + 8) * 64 + oc);
                    float2 o = make_float2(fmaf(nz.x, expf(al[2] + bl0), am[2] + bm0),
                                           fmaf(nz.y, expf(al[3] + bl1), am[3] + bm1));
                    *(float2*)(outp + (size_t)(r + 8) * 64 + oc) = o;
                }
            }
        }
    }
}

// ---------------- launch: pure kernel launches ----------------
extern "C" void kernel_launch(void* const* d_in, const int* in_sizes, int n_in,
                              void* d_out, int out_size) {
    const float* features = (const float*)d_in[0];
    const int*   src      = (const int*)  d_in[1];
    const int*   dst      = (const int*)  d_in[2];
    const float* noise    = (const float*)d_in[3];
    const float* ws0      = (const float*)d_in[4];
    const float* wn0      = (const float*)d_in[5];
    const float* b0       = (const float*)d_in[6];
    const float* ws1      = (const float*)d_in[7];
    const float* wn1      = (const float*)d_in[8];
    const float* b1       = (const float*)d_in[9];
    const float* ws2      = (const float*)d_in[10];
    const float* wn2      = (const float*)d_in[11];
    const float* b2       = (const float*)d_in[12];
    float* out = (float*)d_out;

    const int EB = N_EDGES / 256;
    const int AGG_BLOCKS = (N_NODES * 32 + 255) / 256;

    zero_deg_kernel<<<(N_NODES + 255) / 256, 256>>>();
    prep_weights<<<256, 256>>>(ws0, wn0, ws1, wn1, ws2, wn2, b1, b2);
    conv_kernel<<<(N_NODES * 32 + 255) / 256, 256>>>(features);
    degree_kernel<<<EB, 256>>>(dst);
    scan1_kernel<<<SCAN_NBLK, 1024>>>();
    scan2_kernel<<<1, 64>>>();
    scan3_kernel<<<(N_NODES + 255) / 256, 256>>>();
    fill_kernel<<<EB, 256>>>(src, dst);

    // layer 0 (agg reads fp16 features mirror)
    agg_kernel<<<AGG_BLOCKS, 256>>>();
    mma_gemm_kernel<0><<<GEMM_BLOCKS, 256>>>(features, b0, nullptr, nullptr);

    // layers 1 & 2 fused (agg reads fp16 h mirror written by GEMM-0 epilogue)
    agg_kernel<<<AGG_BLOCKS, 256>>>();
    mma_gemm_kernel<1><<<GEMM_BLOCKS, 256>>>(nullptr, nullptr, noise, out);
}